// round 1
// baseline (speedup 1.0000x reference)
#include <cuda_runtime.h>

#define N_BT  32
#define HWD   1024
#define CHN   64
#define PLANE 65536      /* CHN*HWD */
#define TOT   2097152    /* N_BT*PLANE */

// ---- scratch (module-load allocated, legal) ----
__device__ float g_q[TOT];
__device__ float g_k[TOT];
__device__ float g_v[TOT];
__device__ float g_A[TOT];          // a_c, then a_c + a_s
__device__ float g_Xe[TOT];
__device__ float g_cl[N_BT * 64 * 64];  // channel logits -> m_c in place
__device__ float g_tl[256];             // temporal logits -> m_t in place
__device__ float g_L[N_BT * HWD * HWD]; // 128 MB spatial logits -> m_s in place

// ============================================================
__global__ void k_zero() {
    int i = blockIdx.x * 256 + threadIdx.x;
    if (i < N_BT * 4096) g_cl[i] = 0.f;
}

// ---- QKV: relu(W x + b), written as [n][c][i] (n = b*T+t) ----
__global__ void k_qkv(const float* __restrict__ x,
                      const float* __restrict__ wq, const float* __restrict__ bq,
                      const float* __restrict__ wk, const float* __restrict__ bk,
                      const float* __restrict__ wv, const float* __restrict__ bv) {
    __shared__ float sX[64][64];   // [c][pos]
    __shared__ float sW[64][65];   // [o][c]
    int tid = threadIdx.x;
    int pt = blockIdx.x;
    int n  = pt >> 4;
    int i0 = (pt & 15) << 6;
    int b = n >> 3, t = n & 7;
    const float *w, *bias;
    float* outp;
    if (blockIdx.y == 0)      { w = wq; bias = bq; outp = g_q; }
    else if (blockIdx.y == 1) { w = wk; bias = bk; outp = g_k; }
    else                      { w = wv; bias = bv; outp = g_v; }
    for (int idx = tid; idx < 4096; idx += 256) {
        int c = idx >> 6, p = idx & 63;
        sX[c][p] = x[((b * 64 + c) * 8 + t) * 1024 + i0 + p];
        sW[c][p] = w[idx];   // reuse (c,p) as (o,cin)
    }
    __syncthreads();
    int tx = tid & 15, ty = tid >> 4;
    float acc[4][4] = {};
#pragma unroll
    for (int c = 0; c < 64; c++) {
        float4 a4 = *(const float4*)&sX[c][tx * 4];
        float ra[4] = {a4.x, a4.y, a4.z, a4.w};
        float rb[4];
#pragma unroll
        for (int v = 0; v < 4; v++) rb[v] = sW[ty * 4 + v][c];
#pragma unroll
        for (int v = 0; v < 4; v++)
#pragma unroll
            for (int u = 0; u < 4; u++) acc[v][u] = fmaf(rb[v], ra[u], acc[v][u]);
    }
#pragma unroll
    for (int v = 0; v < 4; v++) {
        int o = ty * 4 + v;
        float bb = bias[o];
#pragma unroll
        for (int u = 0; u < 4; u++)
            outp[n * PLANE + o * HWD + i0 + tx * 4 + u] = fmaxf(acc[v][u] + bb, 0.f);
    }
}

// ---- channel logits: cl[n,c,d] = sum_i q[n,c,i] k[n,d,i] (split-k, atomics) ----
__global__ void k_cl() {
    __shared__ float sQT[64][68];  // [kk][c]
    __shared__ float sKT[64][68];  // [kk][d]
    int n = blockIdx.y;
    int tid = threadIdx.x, tx = tid & 15, ty = tid >> 4;
    float acc[4][4] = {};
    for (int sub = 0; sub < 4; sub++) {
        int k0 = blockIdx.x * 256 + sub * 64;
        __syncthreads();
        for (int idx = tid; idx < 4096; idx += 256) {
            int c = idx >> 6, kk = idx & 63;
            sQT[kk][c] = g_q[n * PLANE + c * HWD + k0 + kk];
            sKT[kk][c] = g_k[n * PLANE + c * HWD + k0 + kk];
        }
        __syncthreads();
#pragma unroll 16
        for (int kk = 0; kk < 64; kk++) {
            float ra[4], rb[4];
#pragma unroll
            for (int v = 0; v < 4; v++) ra[v] = sQT[kk][ty * 4 + v];
#pragma unroll
            for (int u = 0; u < 4; u++) rb[u] = sKT[kk][tx * 4 + u];
#pragma unroll
            for (int v = 0; v < 4; v++)
#pragma unroll
                for (int u = 0; u < 4; u++) acc[v][u] = fmaf(ra[v], rb[u], acc[v][u]);
        }
    }
#pragma unroll
    for (int v = 0; v < 4; v++)
#pragma unroll
        for (int u = 0; u < 4; u++)
            atomicAdd(&g_cl[n * 4096 + (ty * 4 + v) * 64 + tx * 4 + u], acc[v][u]);
}

// ---- softmax over n on (n,c,d) ----
__global__ void k_softmax_c() {
    int p = blockIdx.x * 256 + threadIdx.x;   // (c,d) pair, 0..4095
    float vals[32], mx = -1e30f;
#pragma unroll
    for (int nn = 0; nn < 32; nn++) { vals[nn] = g_cl[nn * 4096 + p]; mx = fmaxf(mx, vals[nn]); }
    float s = 0.f;
#pragma unroll
    for (int nn = 0; nn < 32; nn++) { vals[nn] = __expf(vals[nn] - mx); s += vals[nn]; }
    float inv = 1.f / s;
#pragma unroll
    for (int nn = 0; nn < 32; nn++) g_cl[nn * 4096 + p] = vals[nn] * inv;
}

// ---- a_c[n,c,i] = sum_d m_c[n,c,d] v[n,d,i] -> g_A ----
__global__ void k_ac() {
    __shared__ float sM[64][65];   // [c][d]
    __shared__ float sV[32][128];  // [d][i]
    int n = blockIdx.y, it = blockIdx.x;
    int tid = threadIdx.x, tx = tid & 15, ty = tid >> 4;
    for (int idx = tid; idx < 4096; idx += 256)
        sM[idx >> 6][idx & 63] = g_cl[n * 4096 + idx];
    float acc[4][8] = {};
    for (int dh = 0; dh < 2; dh++) {
        __syncthreads();
        for (int idx4 = tid; idx4 < 1024; idx4 += 256) {
            int d = idx4 >> 5, ii = (idx4 & 31) << 2;
            *(float4*)&sV[d][ii] =
                *(const float4*)&g_v[n * PLANE + (dh * 32 + d) * HWD + it * 128 + ii];
        }
        __syncthreads();
#pragma unroll 8
        for (int d = 0; d < 32; d++) {
            float rm[4];
#pragma unroll
            for (int v = 0; v < 4; v++) rm[v] = sM[ty * 4 + v][dh * 32 + d];
            float4 va = *(const float4*)&sV[d][tx * 8];
            float4 vb = *(const float4*)&sV[d][tx * 8 + 4];
            float rv[8] = {va.x, va.y, va.z, va.w, vb.x, vb.y, vb.z, vb.w};
#pragma unroll
            for (int v = 0; v < 4; v++)
#pragma unroll
                for (int u = 0; u < 8; u++) acc[v][u] = fmaf(rm[v], rv[u], acc[v][u]);
        }
    }
#pragma unroll
    for (int v = 0; v < 4; v++) {
        int c = ty * 4 + v;
#pragma unroll
        for (int u = 0; u < 8; u++)
            g_A[n * PLANE + c * HWD + it * 128 + tx * 8 + u] = acc[v][u];
    }
}

// ---- spatial logits: L[n,i,j] = sum_c q[n,c,i] k[n,c,j] (128x128 tiles) ----
__global__ void k_slogits() {
    __shared__ float sQ[32][132];  // [c][i]
    __shared__ float sK[32][132];  // [c][j]
    int n = blockIdx.z, it = blockIdx.y, jt = blockIdx.x;
    int tid = threadIdx.x, tx = tid & 15, ty = tid >> 4;
    float acc[8][8] = {};
    for (int ch = 0; ch < 2; ch++) {
        __syncthreads();
        for (int idx4 = tid; idx4 < 1024; idx4 += 256) {
            int c = idx4 >> 5, ii = (idx4 & 31) << 2;
            *(float4*)&sQ[c][ii] =
                *(const float4*)&g_q[n * PLANE + (ch * 32 + c) * HWD + it * 128 + ii];
            *(float4*)&sK[c][ii] =
                *(const float4*)&g_k[n * PLANE + (ch * 32 + c) * HWD + jt * 128 + ii];
        }
        __syncthreads();
#pragma unroll 4
        for (int c = 0; c < 32; c++) {
            float4 qa = *(const float4*)&sQ[c][ty * 8];
            float4 qb = *(const float4*)&sQ[c][ty * 8 + 4];
            float4 ka = *(const float4*)&sK[c][tx * 8];
            float4 kb = *(const float4*)&sK[c][tx * 8 + 4];
            float ra[8] = {qa.x, qa.y, qa.z, qa.w, qb.x, qb.y, qb.z, qb.w};
            float rb[8] = {ka.x, ka.y, ka.z, ka.w, kb.x, kb.y, kb.z, kb.w};
#pragma unroll
            for (int v = 0; v < 8; v++)
#pragma unroll
                for (int u = 0; u < 8; u++) acc[v][u] = fmaf(ra[v], rb[u], acc[v][u]);
        }
    }
#pragma unroll
    for (int v = 0; v < 8; v++) {
        int i = it * 128 + ty * 8 + v;
        int base = (n << 20) + i * HWD + jt * 128 + tx * 8;
        float4 w0 = {acc[v][0], acc[v][1], acc[v][2], acc[v][3]};
        float4 w1 = {acc[v][4], acc[v][5], acc[v][6], acc[v][7]};
        *(float4*)&g_L[base]     = w0;
        *(float4*)&g_L[base + 4] = w1;
    }
}

// ---- softmax over n on (n,i,j), in place, register-resident ----
__global__ void k_softmax_s() {
    int idx = blockIdx.x * 256 + threadIdx.x;  // (i,j), 0..2^20-1
    float vals[32], mx = -1e30f;
#pragma unroll
    for (int nn = 0; nn < 32; nn++) { vals[nn] = g_L[(nn << 20) + idx]; mx = fmaxf(mx, vals[nn]); }
    float s = 0.f;
#pragma unroll
    for (int nn = 0; nn < 32; nn++) { vals[nn] = __expf(vals[nn] - mx); s += vals[nn]; }
    float inv = 1.f / s;
#pragma unroll
    for (int nn = 0; nn < 32; nn++) g_L[(nn << 20) + idx] = vals[nn] * inv;
}

// ---- a_s[n,c,i] = sum_j P[n,i,j] v[n,c,j]; g_A += a_s ----
__global__ void k_as() {
    __shared__ float sV[64][36];    // [c][jj]
    __shared__ float sPT[32][132];  // [jj][i]
    int n = blockIdx.y, it = blockIdx.x;
    int tid = threadIdx.x, tx = tid & 15, ty = tid >> 4;
    float acc[4][8] = {};
    for (int jt = 0; jt < 32; jt++) {
        __syncthreads();
        for (int idx = tid; idx < 2048; idx += 256) {
            int c = idx >> 5, jj = idx & 31;
            sV[c][jj] = g_v[n * PLANE + c * HWD + jt * 32 + jj];
        }
        for (int idx = tid; idx < 4096; idx += 256) {
            int i = idx >> 5, jj = idx & 31;
            sPT[jj][i] = g_L[(n << 20) + (it * 128 + i) * HWD + jt * 32 + jj];
        }
        __syncthreads();
#pragma unroll 8
        for (int j = 0; j < 32; j++) {
            float rv[4];
#pragma unroll
            for (int v = 0; v < 4; v++) rv[v] = sV[ty * 4 + v][j];
            float4 pa = *(const float4*)&sPT[j][tx * 8];
            float4 pb = *(const float4*)&sPT[j][tx * 8 + 4];
            float rp[8] = {pa.x, pa.y, pa.z, pa.w, pb.x, pb.y, pb.z, pb.w};
#pragma unroll
            for (int v = 0; v < 4; v++)
#pragma unroll
                for (int u = 0; u < 8; u++) acc[v][u] = fmaf(rv[v], rp[u], acc[v][u]);
        }
    }
#pragma unroll
    for (int v = 0; v < 4; v++) {
        int c = ty * 4 + v;
#pragma unroll
        for (int u = 0; u < 8; u++) {
            int a = n * PLANE + c * HWD + it * 128 + tx * 8 + u;
            g_A[a] = g_A[a] + acc[v][u];
        }
    }
}

// ---- temporal conv (3,1,1) pad 1 + relu -> g_Xe [n][o][i] ----
__global__ void k_tconv(const float* __restrict__ wX, const float* __restrict__ bX) {
    __shared__ float sA[32][132];  // [c][i]
    __shared__ float sW[64][68];   // [o][c]
    int n = blockIdx.y, it = blockIdx.x;
    int b = n >> 3, t = n & 7;
    int tid = threadIdx.x, tx = tid & 15, ty = tid >> 4;
    float acc[4][8] = {};
    for (int kk = 0; kk < 3; kk++) {
        int tp = t + kk - 1;
        if (tp < 0 || tp >= 8) continue;   // uniform per block
        __syncthreads();
        for (int idx = tid; idx < 4096; idx += 256) {
            int o = idx >> 6, c = idx & 63;
            sW[o][c] = wX[o * 192 + c * 3 + kk];
        }
        for (int ch = 0; ch < 2; ch++) {
            __syncthreads();
            for (int idx4 = tid; idx4 < 1024; idx4 += 256) {
                int c = idx4 >> 5, ii = (idx4 & 31) << 2;
                *(float4*)&sA[c][ii] =
                    *(const float4*)&g_A[(b * 8 + tp) * PLANE + (ch * 32 + c) * HWD + it * 128 + ii];
            }
            __syncthreads();
#pragma unroll 4
            for (int c = 0; c < 32; c++) {
                float rw[4];
#pragma unroll
                for (int v = 0; v < 4; v++) rw[v] = sW[ty * 4 + v][ch * 32 + c];
                float4 aa = *(const float4*)&sA[c][tx * 8];
                float4 ab = *(const float4*)&sA[c][tx * 8 + 4];
                float ra[8] = {aa.x, aa.y, aa.z, aa.w, ab.x, ab.y, ab.z, ab.w};
#pragma unroll
                for (int v = 0; v < 4; v++)
#pragma unroll
                    for (int u = 0; u < 8; u++) acc[v][u] = fmaf(rw[v], ra[u], acc[v][u]);
            }
        }
    }
#pragma unroll
    for (int v = 0; v < 4; v++) {
        int o = ty * 4 + v;
        float bb = bX[o];
#pragma unroll
        for (int u = 0; u < 8; u++)
            g_Xe[n * PLANE + o * HWD + it * 128 + tx * 8 + u] = fmaxf(acc[v][u] + bb, 0.f);
    }
}

// ---- temporal logits: tl[b,t,s] = <Xe[b,t,:], Xe[b,s,:]> over 65536 ----
__global__ void k_tl() {
    __shared__ float red[256];
    int id = blockIdx.x;                    // 0..255
    int b = id >> 6, t = (id >> 3) & 7, s = id & 7;
    const float* p = g_Xe + (b * 8 + t) * PLANE;
    const float* q = g_Xe + (b * 8 + s) * PLANE;
    float sum = 0.f;
    for (int d = threadIdx.x * 4; d < PLANE; d += 1024) {
        float4 a = *(const float4*)&p[d];
        float4 c = *(const float4*)&q[d];
        sum += a.x * c.x + a.y * c.y + a.z * c.z + a.w * c.w;
    }
    red[threadIdx.x] = sum;
    __syncthreads();
    for (int st = 128; st > 0; st >>= 1) {
        if (threadIdx.x < st) red[threadIdx.x] += red[threadIdx.x + st];
        __syncthreads();
    }
    if (threadIdx.x == 0) g_tl[id] = red[0];
}

// ---- softmax over b on (b,t,s) ----
__global__ void k_softmax_t() {
    int p = threadIdx.x;  // 64 (t,s) pairs
    float v0 = g_tl[p], v1 = g_tl[64 + p], v2 = g_tl[128 + p], v3 = g_tl[192 + p];
    float mx = fmaxf(fmaxf(v0, v1), fmaxf(v2, v3));
    v0 = __expf(v0 - mx); v1 = __expf(v1 - mx); v2 = __expf(v2 - mx); v3 = __expf(v3 - mx);
    float inv = 1.f / (v0 + v1 + v2 + v3);
    g_tl[p] = v0 * inv; g_tl[64 + p] = v1 * inv;
    g_tl[128 + p] = v2 * inv; g_tl[192 + p] = v3 * inv;
}

// ---- out[b,c,t,i] = sum_s m_t[b,t,s] v[b,s,c,i] ----
__global__ void k_out(float* __restrict__ out) {
    __shared__ float sM[64];
    int gid = blockIdx.x * 256 + threadIdx.x;
    int b = gid >> 16;
    if (threadIdx.x < 64) sM[threadIdx.x] = g_tl[b * 64 + threadIdx.x];
    __syncthreads();
    int rem = gid & 65535;
    int c = rem >> 10, i = rem & 1023;
    float vv[8];
#pragma unroll
    for (int s = 0; s < 8; s++) vv[s] = g_v[(b * 8 + s) * PLANE + c * HWD + i];
#pragma unroll
    for (int t = 0; t < 8; t++) {
        float r = 0.f;
#pragma unroll
        for (int s = 0; s < 8; s++) r = fmaf(sM[t * 8 + s], vv[s], r);
        out[((b * 64 + c) * 8 + t) * HWD + i] = r;
    }
}

// ============================================================
extern "C" void kernel_launch(void* const* d_in, const int* in_sizes, int n_in,
                              void* d_out, int out_size) {
    const float* x  = (const float*)d_in[0];
    const float* wq = (const float*)d_in[1];
    const float* bq = (const float*)d_in[2];
    const float* wk = (const float*)d_in[3];
    const float* bk = (const float*)d_in[4];
    const float* wv = (const float*)d_in[5];
    const float* bv = (const float*)d_in[6];
    const float* wX = (const float*)d_in[7];
    const float* bX = (const float*)d_in[8];
    float* out = (float*)d_out;

    k_zero<<<512, 256>>>();
    k_qkv<<<dim3(512, 3), 256>>>(x, wq, bq, wk, bk, wv, bv);
    k_cl<<<dim3(4, 32), 256>>>();
    k_softmax_c<<<16, 256>>>();
    k_ac<<<dim3(8, 32), 256>>>();
    k_slogits<<<dim3(8, 8, 32), 256>>>();
    k_softmax_s<<<4096, 256>>>();
    k_as<<<dim3(8, 32), 256>>>();
    k_tconv<<<dim3(8, 32), 256>>>(wX, bX);
    k_tl<<<256, 256>>>();
    k_softmax_t<<<1, 64>>>();
    k_out<<<1024, 256>>>(out);
}

// round 2
// speedup vs baseline: 1.1711x; 1.1711x over previous
#include <cuda_runtime.h>
#include <cstdint>

#define N_BT  32
#define HWD   1024
#define CHN   64
#define PLANE 65536      /* CHN*HWD */
#define TOT   2097152    /* N_BT*PLANE */

// ---- scratch (module-load allocated, legal) ----
__device__ float g_qT[TOT];   // [n][i][c]  (transposed for MMA A-operand)
__device__ float g_kT[TOT];   // [n][j][c]
__device__ float g_v [TOT];   // [n][c][i]
__device__ float g_A [TOT];   // a_c, then a_c + a_s   [n][c][i]
__device__ float g_Xe[TOT];   // [n][c][i]
__device__ float g_cl[N_BT * 64 * 64];
__device__ float g_tl[256];
__device__ float g_L [N_BT * HWD * HWD]; // raw spatial logits (128 MB)
__device__ float g_mx [HWD * HWD];       // per-(i,j) max over n
__device__ float g_inv[HWD * HWD];       // per-(i,j) 1/sum

__device__ __forceinline__ float cvt_tf32(float x) {
    uint32_t u;
    asm("cvt.rna.tf32.f32 %0, %1;" : "=r"(u) : "f"(x));
    return __uint_as_float(u);
}

__device__ __forceinline__ void mma_tf32(float* d, const uint32_t* a,
                                         uint32_t b0, uint32_t b1) {
    asm volatile(
        "mma.sync.aligned.m16n8k8.row.col.f32.tf32.tf32.f32 "
        "{%0,%1,%2,%3}, {%4,%5,%6,%7}, {%8,%9}, {%0,%1,%2,%3};\n"
        : "+f"(d[0]), "+f"(d[1]), "+f"(d[2]), "+f"(d[3])
        : "r"(a[0]), "r"(a[1]), "r"(a[2]), "r"(a[3]), "r"(b0), "r"(b1));
}

// ============================================================
__global__ void k_zero() {
    int i = blockIdx.x * 256 + threadIdx.x;
    if (i < N_BT * 4096) g_cl[i] = 0.f;
}

// ---- QKV: relu(W x + b). q,k written transposed [n][i][c]; v as [n][c][i] ----
__global__ void k_qkv(const float* __restrict__ x,
                      const float* __restrict__ wq, const float* __restrict__ bq,
                      const float* __restrict__ wk, const float* __restrict__ bk,
                      const float* __restrict__ wv, const float* __restrict__ bv) {
    __shared__ float sX[64][68];   // [c][pos], also reused as [o][pos] output stage
    __shared__ float sW[64][68];   // [o][c]
    int tid = threadIdx.x;
    int pt = blockIdx.x;
    int n  = pt >> 4;
    int i0 = (pt & 15) << 6;
    int b = n >> 3, t = n & 7;
    const float *w, *bias;
    if (blockIdx.y == 0)      { w = wq; bias = bq; }
    else if (blockIdx.y == 1) { w = wk; bias = bk; }
    else                      { w = wv; bias = bv; }
    for (int idx = tid; idx < 4096; idx += 256) {
        int c = idx >> 6, p = idx & 63;
        sX[c][p] = x[((b * 64 + c) * 8 + t) * 1024 + i0 + p];
        sW[c][p] = w[idx];   // (c,p) reused as (o,cin)
    }
    __syncthreads();
    int tx = tid & 15, ty = tid >> 4;
    float acc[4][4] = {};
#pragma unroll
    for (int c = 0; c < 64; c++) {
        float4 a4 = *(const float4*)&sX[c][tx * 4];
        float ra[4] = {a4.x, a4.y, a4.z, a4.w};
        float rb[4];
#pragma unroll
        for (int v = 0; v < 4; v++) rb[v] = sW[ty * 4 + v][c];
#pragma unroll
        for (int v = 0; v < 4; v++)
#pragma unroll
            for (int u = 0; u < 4; u++) acc[v][u] = fmaf(rb[v], ra[u], acc[v][u]);
    }
    // relu + bias into registers
#pragma unroll
    for (int v = 0; v < 4; v++) {
        float bb = bias[ty * 4 + v];
#pragma unroll
        for (int u = 0; u < 4; u++) acc[v][u] = fmaxf(acc[v][u] + bb, 0.f);
    }
    if (blockIdx.y == 2) {
        // v: [c][i] layout, direct store
#pragma unroll
        for (int v = 0; v < 4; v++)
#pragma unroll
            for (int u = 0; u < 4; u++)
                g_v[n * PLANE + (ty * 4 + v) * HWD + i0 + tx * 4 + u] = acc[v][u];
    } else {
        // q/k: transpose via smem, store [i][c]
        __syncthreads();
#pragma unroll
        for (int v = 0; v < 4; v++)
#pragma unroll
            for (int u = 0; u < 4; u++)
                sX[ty * 4 + v][tx * 4 + u] = acc[v][u];
        __syncthreads();
        float* outp = (blockIdx.y == 0) ? g_qT : g_kT;
        for (int idx = tid; idx < 4096; idx += 256) {
            int li = idx >> 6, o = idx & 63;
            outp[n * PLANE + (i0 + li) * 64 + o] = sX[o][li];
        }
    }
}

// ---- channel logits: cl[n,c,d] = sum_i q[n,c,i] k[n,d,i] (split-k, atomics) ----
__global__ void k_cl() {
    __shared__ float sQT[64][68];  // [kk][c]
    __shared__ float sKT[64][68];  // [kk][d]
    int n = blockIdx.y;
    int tid = threadIdx.x, tx = tid & 15, ty = tid >> 4;
    float acc[4][4] = {};
    for (int sub = 0; sub < 4; sub++) {
        int k0 = blockIdx.x * 256 + sub * 64;
        __syncthreads();
        for (int idx = tid; idx < 4096; idx += 256) {
            int kk = idx >> 6, c = idx & 63;
            sQT[kk][c] = g_qT[n * PLANE + (k0 + kk) * 64 + c];
            sKT[kk][c] = g_kT[n * PLANE + (k0 + kk) * 64 + c];
        }
        __syncthreads();
#pragma unroll 16
        for (int kk = 0; kk < 64; kk++) {
            float ra[4], rb[4];
#pragma unroll
            for (int v = 0; v < 4; v++) ra[v] = sQT[kk][ty * 4 + v];
#pragma unroll
            for (int u = 0; u < 4; u++) rb[u] = sKT[kk][tx * 4 + u];
#pragma unroll
            for (int v = 0; v < 4; v++)
#pragma unroll
                for (int u = 0; u < 4; u++) acc[v][u] = fmaf(ra[v], rb[u], acc[v][u]);
        }
    }
#pragma unroll
    for (int v = 0; v < 4; v++)
#pragma unroll
        for (int u = 0; u < 4; u++)
            atomicAdd(&g_cl[n * 4096 + (ty * 4 + v) * 64 + tx * 4 + u], acc[v][u]);
}

// ---- softmax over n on (n,c,d) ----
__global__ void k_softmax_c() {
    int p = blockIdx.x * 256 + threadIdx.x;
    float vals[32], mx = -1e30f;
#pragma unroll
    for (int nn = 0; nn < 32; nn++) { vals[nn] = g_cl[nn * 4096 + p]; mx = fmaxf(mx, vals[nn]); }
    float s = 0.f;
#pragma unroll
    for (int nn = 0; nn < 32; nn++) { vals[nn] = __expf(vals[nn] - mx); s += vals[nn]; }
    float inv = 1.f / s;
#pragma unroll
    for (int nn = 0; nn < 32; nn++) g_cl[nn * 4096 + p] = vals[nn] * inv;
}

// ---- a_c[n,c,i] = sum_d m_c[n,c,d] v[n,d,i] -> g_A ----
__global__ void k_ac() {
    __shared__ float sM[64][65];
    __shared__ float sV[32][128];
    int n = blockIdx.y, it = blockIdx.x;
    int tid = threadIdx.x, tx = tid & 15, ty = tid >> 4;
    for (int idx = tid; idx < 4096; idx += 256)
        sM[idx >> 6][idx & 63] = g_cl[n * 4096 + idx];
    float acc[4][8] = {};
    for (int dh = 0; dh < 2; dh++) {
        __syncthreads();
        for (int idx4 = tid; idx4 < 1024; idx4 += 256) {
            int d = idx4 >> 5, ii = (idx4 & 31) << 2;
            *(float4*)&sV[d][ii] =
                *(const float4*)&g_v[n * PLANE + (dh * 32 + d) * HWD + it * 128 + ii];
        }
        __syncthreads();
#pragma unroll 8
        for (int d = 0; d < 32; d++) {
            float rm[4];
#pragma unroll
            for (int v = 0; v < 4; v++) rm[v] = sM[ty * 4 + v][dh * 32 + d];
            float4 va = *(const float4*)&sV[d][tx * 8];
            float4 vb = *(const float4*)&sV[d][tx * 8 + 4];
            float rv[8] = {va.x, va.y, va.z, va.w, vb.x, vb.y, vb.z, vb.w};
#pragma unroll
            for (int v = 0; v < 4; v++)
#pragma unroll
                for (int u = 0; u < 8; u++) acc[v][u] = fmaf(rm[v], rv[u], acc[v][u]);
        }
    }
#pragma unroll
    for (int v = 0; v < 4; v++)
#pragma unroll
        for (int u = 0; u < 8; u++)
            g_A[n * PLANE + (ty * 4 + v) * HWD + it * 128 + tx * 8 + u] = acc[v][u];
}

// ---- spatial logits via tf32 MMA: L[n,i,j] = sum_c qT[n,i,c] kT[n,j,c] ----
__global__ void k_slogits() {
    __shared__ float sQ[128][36];  // [i][c-chunk]
    __shared__ float sK[128][36];  // [j][c-chunk]
    int n = blockIdx.z, it = blockIdx.y, jt = blockIdx.x;
    int tid = threadIdx.x;
    int warp = tid >> 5, lane = tid & 31;
    int r = lane >> 2, cc = lane & 3;
    int wi = (warp & 3) * 32;   // 4 warps along i
    int wj = (warp >> 2) * 64;  // 2 warps along j
    float acc[2][8][4] = {};
    const float* qb = g_qT + n * PLANE + (it * 128) * 64;
    const float* kb = g_kT + n * PLANE + (jt * 128) * 64;
    for (int ch = 0; ch < 2; ch++) {
        __syncthreads();
        for (int idx = tid; idx < 4096; idx += 256) {
            int i = idx >> 5, c = idx & 31;
            sQ[i][c] = cvt_tf32(qb[i * 64 + ch * 32 + c]);
            sK[i][c] = cvt_tf32(kb[i * 64 + ch * 32 + c]);
        }
        __syncthreads();
#pragma unroll
        for (int ks = 0; ks < 4; ks++) {
            int kk = ks * 8;
            uint32_t a[2][4];
#pragma unroll
            for (int m = 0; m < 2; m++) {
                int i0 = wi + m * 16;
                a[m][0] = __float_as_uint(sQ[i0 + r][kk + cc]);
                a[m][1] = __float_as_uint(sQ[i0 + r + 8][kk + cc]);
                a[m][2] = __float_as_uint(sQ[i0 + r][kk + cc + 4]);
                a[m][3] = __float_as_uint(sQ[i0 + r + 8][kk + cc + 4]);
            }
#pragma unroll
            for (int t = 0; t < 8; t++) {
                uint32_t b0 = __float_as_uint(sK[wj + t * 8 + r][kk + cc]);
                uint32_t b1 = __float_as_uint(sK[wj + t * 8 + r][kk + cc + 4]);
#pragma unroll
                for (int m = 0; m < 2; m++) mma_tf32(acc[m][t], a[m], b0, b1);
            }
        }
    }
#pragma unroll
    for (int m = 0; m < 2; m++)
#pragma unroll
        for (int t = 0; t < 8; t++) {
            int row = it * 128 + wi + m * 16 + r;
            int col = jt * 128 + wj + t * 8 + cc * 2;
            int base = (n << 20) + row * HWD + col;
            float2 lo = {acc[m][t][0], acc[m][t][1]};
            float2 hi = {acc[m][t][2], acc[m][t][3]};
            *(float2*)&g_L[base] = lo;
            *(float2*)&g_L[base + 8 * HWD] = hi;
        }
}

// ---- per-(i,j) max and 1/sum over n ----
__global__ void k_smax() {
    int idx = blockIdx.x * 256 + threadIdx.x;
    float vals[32], mx = -1e30f;
#pragma unroll
    for (int nn = 0; nn < 32; nn++) { vals[nn] = g_L[(nn << 20) + idx]; mx = fmaxf(mx, vals[nn]); }
    float s = 0.f;
#pragma unroll
    for (int nn = 0; nn < 32; nn++) s += __expf(vals[nn] - mx);
    g_mx[idx] = mx;
    g_inv[idx] = 1.f / s;
}

// ---- a_s via tf32 MMA with fused exp: g_A[n,c,i] += sum_j P[n,i,j] v[n,c,j] ----
__global__ void k_as() {
    __shared__ float sV[64][36];   // [c][j-chunk]
    __shared__ float sP[128][36];  // [i][j-chunk]
    int n = blockIdx.y, it = blockIdx.x;
    int tid = threadIdx.x;
    int warp = tid >> 5, lane = tid & 31;
    int r = lane >> 2, cc = lane & 3;
    int wc = (warp & 1) * 32;    // 2 warps along c (m)
    int wi = (warp >> 1) * 32;   // 4 warps along i (n)
    float acc[2][4][4] = {};
    for (int jc = 0; jc < 32; jc++) {
        int j0 = jc * 32;
        __syncthreads();
        for (int idx = tid; idx < 2048; idx += 256) {
            int c = idx >> 5, jj = idx & 31;
            sV[c][jj] = cvt_tf32(g_v[n * PLANE + c * HWD + j0 + jj]);
        }
        for (int idx = tid; idx < 4096; idx += 256) {
            int i = idx >> 5, jj = idx & 31;
            int gij = (it * 128 + i) * HWD + j0 + jj;
            float l = g_L[(n << 20) + gij];
            float p = __expf(l - g_mx[gij]) * g_inv[gij];
            sP[i][jj] = cvt_tf32(p);
        }
        __syncthreads();
#pragma unroll
        for (int ks = 0; ks < 4; ks++) {
            int kk = ks * 8;
            uint32_t a[2][4];
#pragma unroll
            for (int m = 0; m < 2; m++) {
                int c0 = wc + m * 16;
                a[m][0] = __float_as_uint(sV[c0 + r][kk + cc]);
                a[m][1] = __float_as_uint(sV[c0 + r + 8][kk + cc]);
                a[m][2] = __float_as_uint(sV[c0 + r][kk + cc + 4]);
                a[m][3] = __float_as_uint(sV[c0 + r + 8][kk + cc + 4]);
            }
#pragma unroll
            for (int t = 0; t < 4; t++) {
                uint32_t b0 = __float_as_uint(sP[wi + t * 8 + r][kk + cc]);
                uint32_t b1 = __float_as_uint(sP[wi + t * 8 + r][kk + cc + 4]);
#pragma unroll
                for (int m = 0; m < 2; m++) mma_tf32(acc[m][t], a[m], b0, b1);
            }
        }
    }
#pragma unroll
    for (int m = 0; m < 2; m++)
#pragma unroll
        for (int t = 0; t < 4; t++) {
            int c0 = wc + m * 16 + r;
            int i0 = it * 128 + wi + t * 8 + cc * 2;
            int a0 = n * PLANE + c0 * HWD + i0;
            int a1 = n * PLANE + (c0 + 8) * HWD + i0;
            float2 o0 = *(float2*)&g_A[a0];
            float2 o1 = *(float2*)&g_A[a1];
            o0.x += acc[m][t][0]; o0.y += acc[m][t][1];
            o1.x += acc[m][t][2]; o1.y += acc[m][t][3];
            *(float2*)&g_A[a0] = o0;
            *(float2*)&g_A[a1] = o1;
        }
}

// ---- temporal conv (3,1,1) pad 1 + relu -> g_Xe ----
__global__ void k_tconv(const float* __restrict__ wX, const float* __restrict__ bX) {
    __shared__ float sA[32][132];
    __shared__ float sW[64][68];
    int n = blockIdx.y, it = blockIdx.x;
    int b = n >> 3, t = n & 7;
    int tid = threadIdx.x, tx = tid & 15, ty = tid >> 4;
    float acc[4][8] = {};
    for (int kk = 0; kk < 3; kk++) {
        int tp = t + kk - 1;
        if (tp < 0 || tp >= 8) continue;
        __syncthreads();
        for (int idx = tid; idx < 4096; idx += 256) {
            int o = idx >> 6, c = idx & 63;
            sW[o][c] = wX[o * 192 + c * 3 + kk];
        }
        for (int ch = 0; ch < 2; ch++) {
            __syncthreads();
            for (int idx4 = tid; idx4 < 1024; idx4 += 256) {
                int c = idx4 >> 5, ii = (idx4 & 31) << 2;
                *(float4*)&sA[c][ii] =
                    *(const float4*)&g_A[(b * 8 + tp) * PLANE + (ch * 32 + c) * HWD + it * 128 + ii];
            }
            __syncthreads();
#pragma unroll 4
            for (int c = 0; c < 32; c++) {
                float rw[4];
#pragma unroll
                for (int v = 0; v < 4; v++) rw[v] = sW[ty * 4 + v][ch * 32 + c];
                float4 aa = *(const float4*)&sA[c][tx * 8];
                float4 ab = *(const float4*)&sA[c][tx * 8 + 4];
                float ra[8] = {aa.x, aa.y, aa.z, aa.w, ab.x, ab.y, ab.z, ab.w};
#pragma unroll
                for (int v = 0; v < 4; v++)
#pragma unroll
                    for (int u = 0; u < 8; u++) acc[v][u] = fmaf(rw[v], ra[u], acc[v][u]);
            }
        }
    }
#pragma unroll
    for (int v = 0; v < 4; v++) {
        float bb = bX[ty * 4 + v];
#pragma unroll
        for (int u = 0; u < 8; u++)
            g_Xe[n * PLANE + (ty * 4 + v) * HWD + it * 128 + tx * 8 + u] =
                fmaxf(acc[v][u] + bb, 0.f);
    }
}

// ---- temporal logits ----
__global__ void k_tl() {
    __shared__ float red[256];
    int id = blockIdx.x;
    int b = id >> 6, t = (id >> 3) & 7, s = id & 7;
    const float* p = g_Xe + (b * 8 + t) * PLANE;
    const float* q = g_Xe + (b * 8 + s) * PLANE;
    float sum = 0.f;
    for (int d = threadIdx.x * 4; d < PLANE; d += 1024) {
        float4 a = *(const float4*)&p[d];
        float4 c = *(const float4*)&q[d];
        sum += a.x * c.x + a.y * c.y + a.z * c.z + a.w * c.w;
    }
    red[threadIdx.x] = sum;
    __syncthreads();
    for (int st = 128; st > 0; st >>= 1) {
        if (threadIdx.x < st) red[threadIdx.x] += red[threadIdx.x + st];
        __syncthreads();
    }
    if (threadIdx.x == 0) g_tl[id] = red[0];
}

__global__ void k_softmax_t() {
    int p = threadIdx.x;
    float v0 = g_tl[p], v1 = g_tl[64 + p], v2 = g_tl[128 + p], v3 = g_tl[192 + p];
    float mx = fmaxf(fmaxf(v0, v1), fmaxf(v2, v3));
    v0 = __expf(v0 - mx); v1 = __expf(v1 - mx); v2 = __expf(v2 - mx); v3 = __expf(v3 - mx);
    float inv = 1.f / (v0 + v1 + v2 + v3);
    g_tl[p] = v0 * inv; g_tl[64 + p] = v1 * inv;
    g_tl[128 + p] = v2 * inv; g_tl[192 + p] = v3 * inv;
}

__global__ void k_out(float* __restrict__ out) {
    __shared__ float sM[64];
    int gid = blockIdx.x * 256 + threadIdx.x;
    int b = gid >> 16;
    if (threadIdx.x < 64) sM[threadIdx.x] = g_tl[b * 64 + threadIdx.x];
    __syncthreads();
    int rem = gid & 65535;
    int c = rem >> 10, i = rem & 1023;
    float vv[8];
#pragma unroll
    for (int s = 0; s < 8; s++) vv[s] = g_v[(b * 8 + s) * PLANE + c * HWD + i];
#pragma unroll
    for (int t = 0; t < 8; t++) {
        float rsum = 0.f;
#pragma unroll
        for (int s = 0; s < 8; s++) rsum = fmaf(sM[t * 8 + s], vv[s], rsum);
        out[((b * 64 + c) * 8 + t) * HWD + i] = rsum;
    }
}

// ============================================================
extern "C" void kernel_launch(void* const* d_in, const int* in_sizes, int n_in,
                              void* d_out, int out_size) {
    const float* x  = (const float*)d_in[0];
    const float* wq = (const float*)d_in[1];
    const float* bq = (const float*)d_in[2];
    const float* wk = (const float*)d_in[3];
    const float* bk = (const float*)d_in[4];
    const float* wv = (const float*)d_in[5];
    const float* bv = (const float*)d_in[6];
    const float* wX = (const float*)d_in[7];
    const float* bX = (const float*)d_in[8];
    float* out = (float*)d_out;

    k_zero<<<512, 256>>>();
    k_qkv<<<dim3(512, 3), 256>>>(x, wq, bq, wk, bk, wv, bv);
    k_cl<<<dim3(4, 32), 256>>>();
    k_softmax_c<<<16, 256>>>();
    k_ac<<<dim3(8, 32), 256>>>();
    k_slogits<<<dim3(8, 8, 32), 256>>>();
    k_smax<<<4096, 256>>>();
    k_as<<<dim3(8, 32), 256>>>();
    k_tconv<<<dim3(8, 32), 256>>>(wX, bX);
    k_tl<<<256, 256>>>();
    k_softmax_t<<<1, 64>>>();
    k_out<<<1024, 256>>>(out);
}

// round 4
// speedup vs baseline: 1.7140x; 1.4636x over previous
#include <cuda_runtime.h>
#include <cstdint>

#define N_BT  32
#define HWD   1024
#define CHN   64
#define PLANE 65536      /* CHN*HWD */
#define TOT   2097152    /* N_BT*PLANE */

// ---- scratch (module-load allocated, legal) ----
__device__ float g_qT[TOT];   // [n][i][c]
__device__ float g_kT[TOT];   // [n][j][c]
__device__ float g_v [TOT];   // [n][c][i]
__device__ float g_A [TOT];   // a_c, then a_c + a_s   [n][c][i]
__device__ float g_Xe[TOT];   // [n][c][i]
__device__ float g_cl[N_BT * 64 * 64];
__device__ float g_tl[256];
__device__ float g_L [N_BT * HWD * HWD]; // raw spatial logits (128 MB)
__device__ float g_C [HWD * HWD];        // mx + ln(sum) per (i,j)

__device__ __forceinline__ void mma_tf32(float* d, const uint32_t* a,
                                         uint32_t b0, uint32_t b1) {
    asm volatile(
        "mma.sync.aligned.m16n8k8.row.col.f32.tf32.tf32.f32 "
        "{%0,%1,%2,%3}, {%4,%5,%6,%7}, {%8,%9}, {%0,%1,%2,%3};\n"
        : "+f"(d[0]), "+f"(d[1]), "+f"(d[2]), "+f"(d[3])
        : "r"(a[0]), "r"(a[1]), "r"(a[2]), "r"(a[3]), "r"(b0), "r"(b1));
}

__device__ __forceinline__ void cp_async16(void* smem_dst, const void* gsrc) {
    uint32_t d = (uint32_t)__cvta_generic_to_shared(smem_dst);
    asm volatile("cp.async.cg.shared.global [%0], [%1], 16;\n" :: "r"(d), "l"(gsrc));
}
__device__ __forceinline__ void cp_commit() {
    asm volatile("cp.async.commit_group;\n");
}
__device__ __forceinline__ void cp_wait1() {
    asm volatile("cp.async.wait_group 1;\n");
}

// ============================================================
__global__ void k_zero() {
    int i = blockIdx.x * 256 + threadIdx.x;
    if (i < N_BT * 4096) g_cl[i] = 0.f;
    if (blockIdx.x == 0) g_tl[threadIdx.x] = 0.f;
}

// ---- QKV fused: relu(W x + b). q,k -> [n][i][c]; v -> [n][c][i] ----
__global__ void k_qkv(const float* __restrict__ x,
                      const float* __restrict__ wq, const float* __restrict__ bq,
                      const float* __restrict__ wk, const float* __restrict__ bk,
                      const float* __restrict__ wv, const float* __restrict__ bv) {
    __shared__ float sX[64][68];
    __shared__ float sW[64][68];
    int tid = threadIdx.x;
    int pt = blockIdx.x;
    int n  = pt >> 4;
    int i0 = (pt & 15) << 6;
    int b = n >> 3, t = n & 7;
    const float* ws[3] = {wq, wk, wv};
    const float* bs[3] = {bq, bk, bv};
    for (int idx = tid; idx < 4096; idx += 256) {
        int c = idx >> 6, p = idx & 63;
        sX[c][p] = x[((b * 64 + c) * 8 + t) * 1024 + i0 + p];
    }
    int tx = tid & 15, ty = tid >> 4;
    for (int ph = 0; ph < 3; ph++) {
        __syncthreads();
        for (int idx = tid; idx < 4096; idx += 256)
            sW[idx >> 6][idx & 63] = ws[ph][idx];
        __syncthreads();
        float acc[4][4] = {};
#pragma unroll
        for (int c = 0; c < 64; c++) {
            float4 a4 = *(const float4*)&sX[c][tx * 4];
            float ra[4] = {a4.x, a4.y, a4.z, a4.w};
            float rb[4];
#pragma unroll
            for (int v = 0; v < 4; v++) rb[v] = sW[ty * 4 + v][c];
#pragma unroll
            for (int v = 0; v < 4; v++)
#pragma unroll
                for (int u = 0; u < 4; u++) acc[v][u] = fmaf(rb[v], ra[u], acc[v][u]);
        }
#pragma unroll
        for (int v = 0; v < 4; v++) {
            float bb = bs[ph][ty * 4 + v];
#pragma unroll
            for (int u = 0; u < 4; u++) acc[v][u] = fmaxf(acc[v][u] + bb, 0.f);
        }
        if (ph == 2) {
#pragma unroll
            for (int v = 0; v < 4; v++)
#pragma unroll
                for (int u = 0; u < 4; u++)
                    g_v[n * PLANE + (ty * 4 + v) * HWD + i0 + tx * 4 + u] = acc[v][u];
        } else {
            __syncthreads();
#pragma unroll
            for (int v = 0; v < 4; v++)
#pragma unroll
                for (int u = 0; u < 4; u++)
                    sW[ty * 4 + v][tx * 4 + u] = acc[v][u];
            __syncthreads();
            float* outp = (ph == 0) ? g_qT : g_kT;
            for (int idx = tid; idx < 4096; idx += 256) {
                int li = idx >> 6, o = idx & 63;
                outp[n * PLANE + (i0 + li) * 64 + o] = sW[o][li];
            }
        }
    }
}

// ---- channel logits (split-k atomics) ----
__global__ void k_cl() {
    __shared__ float sQT[64][68];
    __shared__ float sKT[64][68];
    int n = blockIdx.y;
    int tid = threadIdx.x, tx = tid & 15, ty = tid >> 4;
    float acc[4][4] = {};
    for (int sub = 0; sub < 4; sub++) {
        int k0 = blockIdx.x * 256 + sub * 64;
        __syncthreads();
        for (int idx = tid; idx < 4096; idx += 256) {
            int kk = idx >> 6, c = idx & 63;
            sQT[kk][c] = g_qT[n * PLANE + (k0 + kk) * 64 + c];
            sKT[kk][c] = g_kT[n * PLANE + (k0 + kk) * 64 + c];
        }
        __syncthreads();
#pragma unroll 16
        for (int kk = 0; kk < 64; kk++) {
            float ra[4], rb[4];
#pragma unroll
            for (int v = 0; v < 4; v++) ra[v] = sQT[kk][ty * 4 + v];
#pragma unroll
            for (int u = 0; u < 4; u++) rb[u] = sKT[kk][tx * 4 + u];
#pragma unroll
            for (int v = 0; v < 4; v++)
#pragma unroll
                for (int u = 0; u < 4; u++) acc[v][u] = fmaf(ra[v], rb[u], acc[v][u]);
        }
    }
#pragma unroll
    for (int v = 0; v < 4; v++)
#pragma unroll
        for (int u = 0; u < 4; u++)
            atomicAdd(&g_cl[n * 4096 + (ty * 4 + v) * 64 + tx * 4 + u], acc[v][u]);
}

// ---- spatial logits via tf32 MMA + cp.async pipeline ----
__global__ void k_slogits() {
    __shared__ float sb[2][256][20];   // rows 0-127: Q, 128-255: K; K-chunk 16
    int n = blockIdx.z, it = blockIdx.y, jt = blockIdx.x;
    int tid = threadIdx.x;
    const float* qb = g_qT + n * PLANE + (it * 128) * 64;
    const float* kb = g_kT + n * PLANE + (jt * 128) * 64;

    auto stage = [&](int ch) {
        int s = ch & 1;
#pragma unroll
        for (int v = 0; v < 4; v++) {
            int e = tid + v * 256;       // float4 index 0..1023
            int row = e >> 2;
            int c4 = (e & 3) * 4;
            const float* src = (row < 128) ? (qb + row * 64 + ch * 16 + c4)
                                           : (kb + (row - 128) * 64 + ch * 16 + c4);
            cp_async16(&sb[s][row][c4], src);
        }
        cp_commit();
    };
    stage(0); stage(1);

    int warp = tid >> 5, lane = tid & 31;
    int r = lane >> 2, cc = lane & 3;
    int wi = (warp & 3) * 32;
    int wj = (warp >> 2) * 64;
    float acc[2][8][4] = {};

    for (int ch = 0; ch < 4; ch++) {
        cp_wait1();
        __syncthreads();
        int s = ch & 1;
        float (*sQ)[20] = sb[s];
        float (*sK)[20] = sb[s] + 128;
#pragma unroll
        for (int ks = 0; ks < 2; ks++) {
            int kk = ks * 8;
            uint32_t a[2][4];
#pragma unroll
            for (int m = 0; m < 2; m++) {
                int i0 = wi + m * 16;
                a[m][0] = __float_as_uint(sQ[i0 + r][kk + cc]);
                a[m][1] = __float_as_uint(sQ[i0 + r + 8][kk + cc]);
                a[m][2] = __float_as_uint(sQ[i0 + r][kk + cc + 4]);
                a[m][3] = __float_as_uint(sQ[i0 + r + 8][kk + cc + 4]);
            }
#pragma unroll
            for (int t = 0; t < 8; t++) {
                uint32_t b0 = __float_as_uint(sK[wj + t * 8 + r][kk + cc]);
                uint32_t b1 = __float_as_uint(sK[wj + t * 8 + r][kk + cc + 4]);
#pragma unroll
                for (int m = 0; m < 2; m++) mma_tf32(acc[m][t], a[m], b0, b1);
            }
        }
        __syncthreads();
        if (ch + 2 < 4) stage(ch + 2);
        else cp_commit();   // keep group count aligned for wait_group 1
    }
#pragma unroll
    for (int m = 0; m < 2; m++)
#pragma unroll
        for (int t = 0; t < 8; t++) {
            int row = it * 128 + wi + m * 16 + r;
            int col = jt * 128 + wj + t * 8 + cc * 2;
            int base = (n << 20) + row * HWD + col;
            float2 lo = {acc[m][t][0], acc[m][t][1]};
            float2 hi = {acc[m][t][2], acc[m][t][3]};
            *(float2*)&g_L[base] = lo;
            *(float2*)&g_L[base + 8 * HWD] = hi;
        }
}

// ---- softmax over n on (n,c,d) ----
__global__ void k_softmax_c() {
    int p = blockIdx.x * 256 + threadIdx.x;
    float vals[32], mx = -1e30f;
#pragma unroll
    for (int nn = 0; nn < 32; nn++) { vals[nn] = g_cl[nn * 4096 + p]; mx = fmaxf(mx, vals[nn]); }
    float s = 0.f;
#pragma unroll
    for (int nn = 0; nn < 32; nn++) { vals[nn] = __expf(vals[nn] - mx); s += vals[nn]; }
    float inv = 1.f / s;
#pragma unroll
    for (int nn = 0; nn < 32; nn++) g_cl[nn * 4096 + p] = vals[nn] * inv;
}

// ---- a_c -> g_A ----
__global__ void k_ac() {
    __shared__ float sM[64][65];
    __shared__ float sV[32][128];
    int n = blockIdx.y, it = blockIdx.x;
    int tid = threadIdx.x, tx = tid & 15, ty = tid >> 4;
    for (int idx = tid; idx < 4096; idx += 256)
        sM[idx >> 6][idx & 63] = g_cl[n * 4096 + idx];
    float acc[4][8] = {};
    for (int dh = 0; dh < 2; dh++) {
        __syncthreads();
        for (int idx4 = tid; idx4 < 1024; idx4 += 256) {
            int d = idx4 >> 5, ii = (idx4 & 31) << 2;
            *(float4*)&sV[d][ii] =
                *(const float4*)&g_v[n * PLANE + (dh * 32 + d) * HWD + it * 128 + ii];
        }
        __syncthreads();
#pragma unroll 8
        for (int d = 0; d < 32; d++) {
            float rm[4];
#pragma unroll
            for (int v = 0; v < 4; v++) rm[v] = sM[ty * 4 + v][dh * 32 + d];
            float4 va = *(const float4*)&sV[d][tx * 8];
            float4 vb = *(const float4*)&sV[d][tx * 8 + 4];
            float rv[8] = {va.x, va.y, va.z, va.w, vb.x, vb.y, vb.z, vb.w};
#pragma unroll
            for (int v = 0; v < 4; v++)
#pragma unroll
                for (int u = 0; u < 8; u++) acc[v][u] = fmaf(rm[v], rv[u], acc[v][u]);
        }
    }
#pragma unroll
    for (int v = 0; v < 4; v++)
#pragma unroll
        for (int u = 0; u < 8; u++)
            g_A[n * PLANE + (ty * 4 + v) * HWD + it * 128 + tx * 8 + u] = acc[v][u];
}

// ---- per-(i,j): C = mx + ln(sum_n exp(L - mx)) ----
__global__ void k_smax() {
    int idx = blockIdx.x * 256 + threadIdx.x;
    float vals[32], mx = -1e30f;
#pragma unroll
    for (int nn = 0; nn < 32; nn++) { vals[nn] = g_L[(nn << 20) + idx]; mx = fmaxf(mx, vals[nn]); }
    float s = 0.f;
#pragma unroll
    for (int nn = 0; nn < 32; nn++) s += __expf(vals[nn] - mx);
    g_C[idx] = mx + __logf(s);
}

// ---- a_s via tf32 MMA, fused exp, cp.async pipeline; g_A += ----
// RACE FIX vs round 3: A-fragments are prefetched from sV[s] into registers
// BEFORE stage(ch+2) is issued (stage overwrites sL[s]/sV[s]); the MMA then
// consumes only registers + sP (separate buffer).
__global__ void k_as() {
    __shared__ float sL[2][128][20];
    __shared__ float sV[2][64][20];
    __shared__ float sP[128][20];
    int n = blockIdx.y, it = blockIdx.x;
    int tid = threadIdx.x;
    const float* vb = g_v + n * PLANE;
    const float* lb = g_L + (n << 20) + (it * 128) * HWD;

    auto stage = [&](int ch) {
        int s = ch & 1;
        int j0 = ch * 16;
#pragma unroll
        for (int v = 0; v < 2; v++) {
            int e = tid + v * 256;       // 0..511
            int row = e >> 2;
            int c4 = (e & 3) * 4;
            cp_async16(&sL[s][row][c4], lb + row * HWD + j0 + c4);
        }
        {
            int row = tid >> 2;
            int c4 = (tid & 3) * 4;
            cp_async16(&sV[s][row][c4], vb + row * HWD + j0 + c4);
        }
        cp_commit();
    };
    stage(0); stage(1);

    int warp = tid >> 5, lane = tid & 31;
    int r = lane >> 2, cc = lane & 3;
    int wc = (warp & 1) * 32;
    int wi = (warp >> 1) * 32;
    float acc[2][4][4] = {};

    for (int ch = 0; ch < 64; ch++) {
        cp_wait1();
        __syncthreads();
        int s = ch & 1;
        // prefetch A fragments (V) into registers from sV[s]
        uint32_t areg[2][2][4];   // [ks][m][frag]
#pragma unroll
        for (int ks = 0; ks < 2; ks++) {
            int kk = ks * 8;
#pragma unroll
            for (int m = 0; m < 2; m++) {
                int c0 = wc + m * 16;
                areg[ks][m][0] = __float_as_uint(sV[s][c0 + r][kk + cc]);
                areg[ks][m][1] = __float_as_uint(sV[s][c0 + r + 8][kk + cc]);
                areg[ks][m][2] = __float_as_uint(sV[s][c0 + r][kk + cc + 4]);
                areg[ks][m][3] = __float_as_uint(sV[s][c0 + r + 8][kk + cc + 4]);
            }
        }
        // convert raw logits -> probabilities in sP
#pragma unroll
        for (int v = 0; v < 8; v++) {
            int e = tid + v * 256;
            int row = e >> 4, jj = e & 15;
            float Cv = g_C[(it * 128 + row) * HWD + ch * 16 + jj];
            sP[row][jj] = __expf(sL[s][row][jj] - Cv);
        }
        __syncthreads();
        if (ch + 2 < 64) stage(ch + 2);
        else cp_commit();
#pragma unroll
        for (int ks = 0; ks < 2; ks++) {
            int kk = ks * 8;
#pragma unroll
            for (int t = 0; t < 4; t++) {
                uint32_t b0 = __float_as_uint(sP[wi + t * 8 + r][kk + cc]);
                uint32_t b1 = __float_as_uint(sP[wi + t * 8 + r][kk + cc + 4]);
#pragma unroll
                for (int m = 0; m < 2; m++) mma_tf32(acc[m][t], areg[ks][m], b0, b1);
            }
        }
    }
#pragma unroll
    for (int m = 0; m < 2; m++)
#pragma unroll
        for (int t = 0; t < 4; t++) {
            int c0 = wc + m * 16 + r;
            int i0 = it * 128 + wi + t * 8 + cc * 2;
            int a0 = n * PLANE + c0 * HWD + i0;
            int a1 = n * PLANE + (c0 + 8) * HWD + i0;
            float2 o0 = *(float2*)&g_A[a0];
            float2 o1 = *(float2*)&g_A[a1];
            o0.x += acc[m][t][0]; o0.y += acc[m][t][1];
            o1.x += acc[m][t][2]; o1.y += acc[m][t][3];
            *(float2*)&g_A[a0] = o0;
            *(float2*)&g_A[a1] = o1;
        }
}

// ---- temporal conv (3,1,1) pad 1 + relu -> g_Xe ----
__global__ void k_tconv(const float* __restrict__ wX, const float* __restrict__ bX) {
    __shared__ float sA[32][132];
    __shared__ float sW[64][68];
    int n = blockIdx.y, it = blockIdx.x;
    int b = n >> 3, t = n & 7;
    int tid = threadIdx.x, tx = tid & 15, ty = tid >> 4;
    float acc[4][8] = {};
    for (int kk = 0; kk < 3; kk++) {
        int tp = t + kk - 1;
        if (tp < 0 || tp >= 8) continue;
        __syncthreads();
        for (int idx = tid; idx < 4096; idx += 256) {
            int o = idx >> 6, c = idx & 63;
            sW[o][c] = wX[o * 192 + c * 3 + kk];
        }
        for (int ch = 0; ch < 2; ch++) {
            __syncthreads();
            for (int idx4 = tid; idx4 < 1024; idx4 += 256) {
                int c = idx4 >> 5, ii = (idx4 & 31) << 2;
                *(float4*)&sA[c][ii] =
                    *(const float4*)&g_A[(b * 8 + tp) * PLANE + (ch * 32 + c) * HWD + it * 128 + ii];
            }
            __syncthreads();
#pragma unroll 4
            for (int c = 0; c < 32; c++) {
                float rw[4];
#pragma unroll
                for (int v = 0; v < 4; v++) rw[v] = sW[ty * 4 + v][ch * 32 + c];
                float4 aa = *(const float4*)&sA[c][tx * 8];
                float4 ab = *(const float4*)&sA[c][tx * 8 + 4];
                float ra[8] = {aa.x, aa.y, aa.z, aa.w, ab.x, ab.y, ab.z, ab.w};
#pragma unroll
                for (int v = 0; v < 4; v++)
#pragma unroll
                    for (int u = 0; u < 8; u++) acc[v][u] = fmaf(rw[v], ra[u], acc[v][u]);
            }
        }
    }
#pragma unroll
    for (int v = 0; v < 4; v++) {
        float bb = bX[ty * 4 + v];
#pragma unroll
        for (int u = 0; u < 8; u++)
            g_Xe[n * PLANE + (ty * 4 + v) * HWD + it * 128 + tx * 8 + u] =
                fmaxf(acc[v][u] + bb, 0.f);
    }
}

// ---- temporal Gram: g_tl[b,t,s] += partial dot over d-slice ----
__global__ void k_tl() {
    __shared__ float sXe[8][1032];
    int b = blockIdx.y;
    int d0 = blockIdx.x * 1024;
    int tid = threadIdx.x;
    for (int v = 0; v < 8; v++) {
        int e = tid + v * 256;          // float4 idx 0..2047
        int t = e >> 8;
        int d4 = (e & 255) * 4;
        *(float4*)&sXe[t][d4] = *(const float4*)&g_Xe[(b * 8 + t) * PLANE + d0 + d4];
    }
    __syncthreads();
    int p = tid >> 2, sub = tid & 3;
    int t = p >> 3, s = p & 7;
    float acc = 0.f;
#pragma unroll 8
    for (int it = 0; it < 64; it++) {
        int col = sub * 4 + it * 16;
        float4 a = *(const float4*)&sXe[t][col];
        float4 c = *(const float4*)&sXe[s][col];
        acc += a.x * c.x + a.y * c.y + a.z * c.z + a.w * c.w;
    }
    acc += __shfl_xor_sync(0xffffffff, acc, 1);
    acc += __shfl_xor_sync(0xffffffff, acc, 2);
    if (sub == 0) atomicAdd(&g_tl[b * 64 + p], acc);
}

__global__ void k_softmax_t() {
    int p = threadIdx.x;
    float v0 = g_tl[p], v1 = g_tl[64 + p], v2 = g_tl[128 + p], v3 = g_tl[192 + p];
    float mx = fmaxf(fmaxf(v0, v1), fmaxf(v2, v3));
    v0 = __expf(v0 - mx); v1 = __expf(v1 - mx); v2 = __expf(v2 - mx); v3 = __expf(v3 - mx);
    float inv = 1.f / (v0 + v1 + v2 + v3);
    g_tl[p] = v0 * inv; g_tl[64 + p] = v1 * inv;
    g_tl[128 + p] = v2 * inv; g_tl[192 + p] = v3 * inv;
}

__global__ void k_out(float* __restrict__ out) {
    __shared__ float sM[64];
    int gid = blockIdx.x * 256 + threadIdx.x;
    int b = gid >> 16;
    if (threadIdx.x < 64) sM[threadIdx.x] = g_tl[b * 64 + threadIdx.x];
    __syncthreads();
    int rem = gid & 65535;
    int c = rem >> 10, i = rem & 1023;
    float vv[8];
#pragma unroll
    for (int s = 0; s < 8; s++) vv[s] = g_v[(b * 8 + s) * PLANE + c * HWD + i];
#pragma unroll
    for (int t = 0; t < 8; t++) {
        float rsum = 0.f;
#pragma unroll
        for (int s = 0; s < 8; s++) rsum = fmaf(sM[t * 8 + s], vv[s], rsum);
        out[((b * 64 + c) * 8 + t) * HWD + i] = rsum;
    }
}

// ============================================================
extern "C" void kernel_launch(void* const* d_in, const int* in_sizes, int n_in,
                              void* d_out, int out_size) {
    const float* x  = (const float*)d_in[0];
    const float* wq = (const float*)d_in[1];
    const float* bq = (const float*)d_in[2];
    const float* wk = (const float*)d_in[3];
    const float* bk = (const float*)d_in[4];
    const float* wv = (const float*)d_in[5];
    const float* bv = (const float*)d_in[6];
    const float* wX = (const float*)d_in[7];
    const float* bX = (const float*)d_in[8];
    float* out = (float*)d_out;

    k_zero<<<512, 256>>>();                                // 0
    k_qkv<<<512, 256>>>(x, wq, bq, wk, bk, wv, bv);        // 1
    k_cl<<<dim3(4, 32), 256>>>();                          // 2
    k_slogits<<<dim3(8, 8, 32), 256>>>();                  // 3  <- ncu capture slot
    k_softmax_c<<<16, 256>>>();                            // 4
    k_ac<<<dim3(8, 32), 256>>>();                          // 5
    k_smax<<<4096, 256>>>();                               // 6
    k_as<<<dim3(8, 32), 256>>>();                          // 7
    k_tconv<<<dim3(8, 32), 256>>>(wX, bX);                 // 8
    k_tl<<<dim3(64, 4), 256>>>();                          // 9
    k_softmax_t<<<1, 64>>>();                              // 10
    k_out<<<1024, 256>>>(out);                             // 11
}